// round 1
// baseline (speedup 1.0000x reference)
#include <cuda_runtime.h>
#include <cstdint>
#include <cstddef>

#define BB 32
#define NN 25200
#define NCC 20
#define KK 1024
#define MAXDET 300
#define CONF_T 0.001f
#define IOU_T 0.45f

// ---------- scratch (static device allocations; no cudaMalloc) ----------
__device__ float         g_conf[BB * NN];
__device__ unsigned char g_lab [BB * NN];
__device__ float4        g_tbox[BB * KK];
__device__ float         g_tsc [BB * KK];
__device__ int           g_tlb [BB * KK];
__device__ unsigned      g_msk [BB * KK * 32];   // 4 MB suppression bitmask

// ---------- kernel A: scores + argmax labels (memory-bound full read) ----------
__global__ void k_score(const float* __restrict__ pred) {
    __shared__ float s[256 * 25];
    size_t base = (size_t)blockIdx.x * (256 * 25);
    for (int k = threadIdx.x; k < 256 * 25; k += 256) s[k] = pred[base + k];
    __syncthreads();
    const float* row = s + threadIdx.x * 25;
    float obj  = row[4];
    float best = row[5];
    int   bl   = 0;
#pragma unroll
    for (int c = 1; c < NCC; c++) {
        float v = row[5 + c];
        if (v > best) { best = v; bl = c; }  // first-max like jnp.argmax
    }
    float conf = __fmul_rn(obj, best);
    size_t r = (size_t)blockIdx.x * 256 + threadIdx.x;
    g_conf[r] = conf;
    g_lab[r]  = (unsigned char)bl;
}

// ---------- kernel B1: exact stable top-1024 per batch (bucket select + bitonic) ----------
__global__ void k_topk(const float* __restrict__ pred) {
    extern __shared__ unsigned sh[];
    unsigned* hist  = sh;                 // 32768 words (128 KB)
    unsigned* chunk = sh + 32768;         // 1024 words
    int*      ctrl  = (int*)(sh + 32768 + 1024);  // [0]=cstar [1]=T [2]=cnt
    unsigned long long* cand = (unsigned long long*)sh;  // overlays hist (8192 keys)

    int b = blockIdx.x;
    int tid = threadIdx.x;
    const float* sc = g_conf + (size_t)b * NN;

    for (int k = tid; k < 32768; k += 1024) hist[k] = 0;
    if (tid < 16) ctrl[tid] = (tid == 0) ? -1 : 0;
    __syncthreads();

    // pass 1: histogram of float bits >>15 (positive scores are order-preserving)
    for (int n = tid; n < NN; n += 1024) {
        float v = sc[n];
        if (v > CONF_T) atomicAdd(&hist[__float_as_uint(v) >> 15], 1u);
    }
    __syncthreads();

    // per-thread chunk sums then suffix scan (Hillis-Steele)
    unsigned sum = 0;
    {
        unsigned* hb = hist + tid * 32;
#pragma unroll
        for (int q = 0; q < 32; q++) sum += hb[q];
    }
    chunk[tid] = sum;
    __syncthreads();
    for (int off = 1; off < 1024; off <<= 1) {
        unsigned add = (tid + off < 1024) ? chunk[tid + off] : 0u;
        __syncthreads();
        chunk[tid] += add;
        __syncthreads();
    }
    if (chunk[tid] >= KK) atomicMax(&ctrl[0], tid);
    __syncthreads();
    if (tid == 0) {
        int cs = ctrl[0];
        int T = 0;
        if (cs >= 0) {
            unsigned running = (cs < 1023) ? chunk[cs + 1] : 0u;
            for (int bk = cs * 32 + 31; bk >= cs * 32; bk--) {
                running += hist[bk];
                if (running >= KK) { T = bk; break; }
            }
        }
        ctrl[1] = T;
        ctrl[2] = 0;
    }
    __syncthreads();
    unsigned T = (unsigned)ctrl[1];
    __syncthreads();   // hist reads done; cand may now overlay hist

    // pass 2: collect candidates with stable-tiebreak keys
    for (int n = tid; n < NN; n += 1024) {
        float v = sc[n];
        if (v > CONF_T && (__float_as_uint(v) >> 15) >= T) {
            int p = atomicAdd(&ctrl[2], 1);
            if (p < 8192)
                cand[p] = ((unsigned long long)__float_as_uint(v) << 32)
                        | (unsigned long long)(0xFFFFFFFFu - (unsigned)n);
        }
    }
    __syncthreads();
    int cnt = ctrl[2]; if (cnt > 8192) cnt = 8192;
    int n2 = 1024; while (n2 < cnt) n2 <<= 1;
    for (int p = cnt + tid; p < n2; p += 1024) cand[p] = 0ull;
    __syncthreads();

    // bitonic sort, descending
    for (int k = 2; k <= n2; k <<= 1) {
        for (int j = k >> 1; j > 0; j >>= 1) {
            for (int t = tid; t < n2; t += 1024) {
                int ixj = t ^ j;
                if (ixj > t) {
                    unsigned long long a = cand[t], c = cand[ixj];
                    if (((t & k) == 0) ? (a < c) : (a > c)) { cand[t] = c; cand[ixj] = a; }
                }
            }
            __syncthreads();
        }
    }

    // emit top-1024: score, label, xywh->xyxy (non-fused to match ref)
    {
        unsigned long long key = cand[tid];
        unsigned sb = (unsigned)(key >> 32);
        float score; int n;
        if (sb) { score = __uint_as_float(sb); n = (int)(0xFFFFFFFFu - (unsigned)key); }
        else    { score = -1.0f; n = 0; }
        const float* pr = pred + ((size_t)b * NN + n) * 25;
        float x = pr[0], y = pr[1], w = pr[2], h = pr[3];
        float hw = __fmul_rn(w, 0.5f), hh = __fmul_rn(h, 0.5f);
        int idx = b * KK + tid;
        g_tbox[idx] = make_float4(__fsub_rn(x, hw), __fsub_rn(y, hh),
                                  __fadd_rn(x, hw), __fadd_rn(y, hh));
        g_tsc[idx]  = score;
        g_tlb[idx]  = (int)g_lab[(size_t)b * NN + n];
    }
}

// ---------- kernel B2: pairwise IoU suppression bitmask (512 blocks) ----------
__global__ void k_iou() {
    __shared__ float sx1[KK], sy1[KK], sx2[KK], sy2[KK], sar[KK];
    int b = blockIdx.y;
    int tid = threadIdx.x;
    for (int q = tid; q < KK; q += 256) {
        float4 bx = g_tbox[b * KK + q];
        float off = __fmul_rn((float)g_tlb[b * KK + q], 4096.0f);
        // offsets are applied BEFORE area: fp32 quantization at +label*4096 must match ref
        float ox1 = __fadd_rn(bx.x, off), oy1 = __fadd_rn(bx.y, off);
        float ox2 = __fadd_rn(bx.z, off), oy2 = __fadd_rn(bx.w, off);
        sx1[q] = ox1; sy1[q] = oy1; sx2[q] = ox2; sy2[q] = oy2;
        sar[q] = __fmul_rn(__fsub_rn(ox2, ox1), __fsub_rn(oy2, oy1));
    }
    __syncthreads();

    int i = blockIdx.x * 64 + (tid & 63);
    int wstart = tid >> 6;   // uniform per warp -> broadcast smem loads
    float ix1 = sx1[i], iy1 = sy1[i], ix2 = sx2[i], iy2 = sy2[i], ai = sar[i];
    unsigned* mrow = g_msk + ((size_t)b * KK + i) * 32;

    for (int w = wstart; w < 32; w += 4) {
        unsigned bits = 0;
        int jbase = w * 32;
        int bj0 = (i >= jbase) ? (i - jbase + 1) : 0;
        for (int bj = bj0; bj < 32; bj++) {
            int j = jbase + bj;
            float ltx = fmaxf(ix1, sx1[j]), lty = fmaxf(iy1, sy1[j]);
            float rbx = fminf(ix2, sx2[j]), rby = fminf(iy2, sy2[j]);
            float ww = fmaxf(__fsub_rn(rbx, ltx), 0.0f);
            float hh = fmaxf(__fsub_rn(rby, lty), 0.0f);
            float inter = __fmul_rn(ww, hh);
            float den = __fadd_rn(__fsub_rn(__fadd_rn(ai, sar[j]), inter), 1e-9f);
            float iou = inter / den;            // IEEE div: bit-match reference compare
            if (iou > IOU_T) bits |= (1u << bj);
        }
        mrow[w] = bits;
    }
}

// ---------- kernel B3/4: greedy NMS scan + clip/filter + top-300 compaction ----------
__global__ void k_nms(const int* __restrict__ imw, const int* __restrict__ imh,
                      float* __restrict__ out) {
    extern __shared__ unsigned sh[];
    unsigned* smask = sh;                    // 32768 words (128 KB)
    unsigned* keepw = sh + 32768;            // 32
    unsigned* wcnt  = sh + 32800;            // 32
    unsigned* wbal  = sh + 32832;            // 32
    int*      ctrl  = (int*)(sh + 32864);    // 4
    float4*   cbox  = (float4*)(sh + 32880); // 300, 16B-aligned
    float*    cscore = (float*)(cbox + MAXDET);
    int*      clabel = (int*)(cscore + MAXDET);

    int b = blockIdx.x, tid = threadIdx.x;
    int lane = tid & 31, wid = tid >> 5;

    for (int k = tid; k < 32768; k += 1024) smask[k] = g_msk[(size_t)b * 32768 + k];

    float score = g_tsc[b * KK + tid];
    bool kp = score > CONF_T;
    unsigned bal = __ballot_sync(0xffffffffu, kp);
    if (lane == 0) keepw[wid] = bal;
    __syncthreads();

    // single-warp register-resident greedy scan (lane owns one 32-bit keep word)
    if (wid == 0) {
        unsigned kw = keepw[lane];
        for (int wi = 0; wi < 32; wi++) {
            unsigned active = __shfl_sync(0xffffffffu, kw, wi);
            while (active) {
                int bit = __ffs(active) - 1;
                int i = wi * 32 + bit;
                kw &= ~smask[i * 32 + lane];             // conflict-free row read
                active = __shfl_sync(0xffffffffu, kw, wi);
                active &= (0xFFFFFFFEu << bit);
            }
        }
        keepw[lane] = kw;
    }
    __syncthreads();

    bool keep = (keepw[tid >> 5] >> (tid & 31)) & 1u;
    float fw = (float)(*imw), fh = (float)(*imh);
    float4 bx = g_tbox[b * KK + tid];
    float x1c = fminf(fmaxf(bx.x, 0.0f), fw);
    float y1c = fminf(fmaxf(bx.y, 0.0f), fh);
    float x2c = fminf(fmaxf(bx.z, 0.0f), fw);
    float y2c = fminf(fmaxf(bx.w, 0.0f), fh);
    float bw  = __fsub_rn(x2c, x1c);
    float bh2 = __fsub_rn(y2c, y1c);
    bool valid = keep && (bw > 0.0f) && (bh2 > 0.0f) && (bw >= 1.0f) && (bh2 >= 1.0f);

    unsigned vb = __ballot_sync(0xffffffffu, valid);
    if (lane == 0) { wcnt[wid] = __popc(vb); wbal[wid] = vb; }
    __syncthreads();
    if (tid == 0) {
        int acc = 0;
        for (int q = 0; q < 32; q++) { int c = wcnt[q]; wcnt[q] = acc; acc += c; }
        ctrl[0] = acc;
    }
    __syncthreads();
    if (valid) {
        int rank = wcnt[wid] + __popc(wbal[wid] & ((1u << lane) - 1u));
        if (rank < MAXDET) {
            cbox[rank]   = make_float4(x1c, y1c, x2c, y2c);
            cscore[rank] = score;
            clabel[rank] = g_tlb[b * KK + tid];
        }
    }
    __syncthreads();

    int total = ctrl[0]; if (total > MAXDET) total = MAXDET;
    if (tid < MAXDET) {
        float4 ob; float os, ol, ov;
        if (tid < total) { ob = cbox[tid]; os = cscore[tid]; ol = (float)clabel[tid]; ov = 1.0f; }
        else             { ob = make_float4(0,0,0,0); os = 0.0f; ol = 0.0f; ov = 0.0f; }
        float* obox = out + ((size_t)b * MAXDET + tid) * 4;
        obox[0] = ob.x; obox[1] = ob.y; obox[2] = ob.z; obox[3] = ob.w;
        out[BB * MAXDET * 4 + b * MAXDET + tid] = os;   // det_scores
        out[BB * MAXDET * 5 + b * MAXDET + tid] = ol;   // det_labels (as f32)
        out[BB * MAXDET * 6 + b * MAXDET + tid] = ov;   // vm (as f32)
    }
}

extern "C" void kernel_launch(void* const* d_in, const int* in_sizes, int n_in,
                              void* d_out, int out_size) {
    const float* pred = (const float*)d_in[0];
    const int*   imh  = (const int*)d_in[1];
    const int*   imw  = (const int*)d_in[2];
    float* out = (float*)d_out;

    cudaFuncSetAttribute((const void*)k_topk,
                         cudaFuncAttributeMaxDynamicSharedMemorySize, 135232);
    cudaFuncSetAttribute((const void*)k_nms,
                         cudaFuncAttributeMaxDynamicSharedMemorySize, 139264);

    k_score<<<(BB * NN) / 256, 256>>>(pred);
    k_topk<<<BB, 1024, 135232>>>(pred);
    k_iou<<<dim3(16, BB), 256>>>();
    k_nms<<<BB, 1024, 139264>>>(imw, imh, out);
}

// round 2
// speedup vs baseline: 1.4986x; 1.4986x over previous
#include <cuda_runtime.h>
#include <cstdint>
#include <cstddef>

#define BB 32
#define NN 25200
#define NCC 20
#define KK 1024
#define MAXDET 300
#define CONF_T 0.001f
#define IOU_T 0.45f

// ---------- scratch (static device allocations; no cudaMalloc) ----------
__device__ float         g_conf[BB * NN];
__device__ unsigned char g_lab [BB * NN];
__device__ float4        g_tbox[BB * KK];
__device__ float         g_tsc [BB * KK];
__device__ int           g_tlb [BB * KK];
__device__ unsigned      g_msk [BB * KK * 32];   // 4 MB TRANSPOSED mask: [b][w*1024+j], bit bi => i=32w+bi suppresses j (i<j)

// ---------- kernel A: scores + argmax labels (memory-bound full read, float4) ----------
__global__ void k_score(const float* __restrict__ pred) {
    __shared__ float s[256 * 25];
    size_t base4 = (size_t)blockIdx.x * 1600;           // 6400 floats = 1600 float4
    const float4* p4 = (const float4*)pred + base4;
    float4* s4 = (float4*)s;
    for (int k = threadIdx.x; k < 1600; k += 256) s4[k] = p4[k];
    __syncthreads();
    const float* row = s + threadIdx.x * 25;
    float obj  = row[4];
    float best = row[5];
    int   bl   = 0;
#pragma unroll
    for (int c = 1; c < NCC; c++) {
        float v = row[5 + c];
        if (v > best) { best = v; bl = c; }  // first-max like jnp.argmax
    }
    float conf = __fmul_rn(obj, best);
    size_t r = (size_t)blockIdx.x * 256 + threadIdx.x;
    g_conf[r] = conf;
    g_lab[r]  = (unsigned char)bl;
}

// ---------- kernel B1: exact stable top-1024 per batch (bucket select + bitonic) ----------
__global__ void k_topk(const float* __restrict__ pred) {
    extern __shared__ unsigned sh[];
    unsigned* hist  = sh;                 // 32768 words (128 KB)
    unsigned* chunk = sh + 32768;         // 1024 words
    int*      ctrl  = (int*)(sh + 32768 + 1024);  // [0]=cstar [1]=T [2]=cnt
    unsigned long long* cand = (unsigned long long*)sh;  // overlays hist (8192 keys)

    int b = blockIdx.x;
    int tid = threadIdx.x;
    const float* sc = g_conf + (size_t)b * NN;

    for (int k = tid; k < 32768; k += 1024) hist[k] = 0;
    if (tid < 16) ctrl[tid] = (tid == 0) ? -1 : 0;
    __syncthreads();

    // pass 1: histogram of float bits >>15 (positive scores are order-preserving)
    for (int n = tid; n < NN; n += 1024) {
        float v = sc[n];
        if (v > CONF_T) atomicAdd(&hist[__float_as_uint(v) >> 15], 1u);
    }
    __syncthreads();

    // per-thread chunk sums then suffix scan (Hillis-Steele)
    unsigned sum = 0;
    {
        unsigned* hb = hist + tid * 32;
#pragma unroll
        for (int q = 0; q < 32; q++) sum += hb[q];
    }
    chunk[tid] = sum;
    __syncthreads();
    for (int off = 1; off < 1024; off <<= 1) {
        unsigned add = (tid + off < 1024) ? chunk[tid + off] : 0u;
        __syncthreads();
        chunk[tid] += add;
        __syncthreads();
    }
    if (chunk[tid] >= KK) atomicMax(&ctrl[0], tid);
    __syncthreads();
    if (tid == 0) {
        int cs = ctrl[0];
        int T = 0;
        if (cs >= 0) {
            unsigned running = (cs < 1023) ? chunk[cs + 1] : 0u;
            for (int bk = cs * 32 + 31; bk >= cs * 32; bk--) {
                running += hist[bk];
                if (running >= KK) { T = bk; break; }
            }
        }
        ctrl[1] = T;
        ctrl[2] = 0;
    }
    __syncthreads();
    unsigned T = (unsigned)ctrl[1];
    __syncthreads();   // hist reads done; cand may now overlay hist

    // pass 2: collect candidates with stable-tiebreak keys
    for (int n = tid; n < NN; n += 1024) {
        float v = sc[n];
        if (v > CONF_T && (__float_as_uint(v) >> 15) >= T) {
            int p = atomicAdd(&ctrl[2], 1);
            if (p < 8192)
                cand[p] = ((unsigned long long)__float_as_uint(v) << 32)
                        | (unsigned long long)(0xFFFFFFFFu - (unsigned)n);
        }
    }
    __syncthreads();
    int cnt = ctrl[2]; if (cnt > 8192) cnt = 8192;
    int n2 = 1024; while (n2 < cnt) n2 <<= 1;
    for (int p = cnt + tid; p < n2; p += 1024) cand[p] = 0ull;
    __syncthreads();

    // bitonic sort, descending
    for (int k = 2; k <= n2; k <<= 1) {
        for (int j = k >> 1; j > 0; j >>= 1) {
            for (int t = tid; t < n2; t += 1024) {
                int ixj = t ^ j;
                if (ixj > t) {
                    unsigned long long a = cand[t], c = cand[ixj];
                    if (((t & k) == 0) ? (a < c) : (a > c)) { cand[t] = c; cand[ixj] = a; }
                }
            }
            __syncthreads();
        }
    }

    // emit top-1024: score, label, xywh->xyxy (non-fused to match ref)
    {
        unsigned long long key = cand[tid];
        unsigned sb = (unsigned)(key >> 32);
        float score; int n;
        if (sb) { score = __uint_as_float(sb); n = (int)(0xFFFFFFFFu - (unsigned)key); }
        else    { score = -1.0f; n = 0; }
        const float* pr = pred + ((size_t)b * NN + n) * 25;
        float x = pr[0], y = pr[1], w = pr[2], h = pr[3];
        float hw = __fmul_rn(w, 0.5f), hh = __fmul_rn(h, 0.5f);
        int idx = b * KK + tid;
        g_tbox[idx] = make_float4(__fsub_rn(x, hw), __fsub_rn(y, hh),
                                  __fadd_rn(x, hw), __fadd_rn(y, hh));
        g_tsc[idx]  = score;
        g_tlb[idx]  = (int)g_lab[(size_t)b * NN + n];
    }
}

// ---------- kernel B2: pairwise IoU -> TRANSPOSED suppression mask ----------
// g_msk[b][w*1024+j] bit bi set <=> i=32w+bi < j AND iou(i,j) > thr
__global__ void k_iou() {
    __shared__ float sx1[KK], sy1[KK], sx2[KK], sy2[KK], sar[KK];
    int b = blockIdx.y;
    int tid = threadIdx.x;
    for (int q = tid; q < KK; q += 256) {
        float4 bx = g_tbox[b * KK + q];
        float off = __fmul_rn((float)g_tlb[b * KK + q], 4096.0f);
        // offsets applied BEFORE area: fp32 quantization at +label*4096 must match ref
        float ox1 = __fadd_rn(bx.x, off), oy1 = __fadd_rn(bx.y, off);
        float ox2 = __fadd_rn(bx.z, off), oy2 = __fadd_rn(bx.w, off);
        sx1[q] = ox1; sy1[q] = oy1; sx2[q] = ox2; sy2[q] = oy2;
        sar[q] = __fmul_rn(__fsub_rn(ox2, ox1), __fsub_rn(oy2, oy1));
    }
    __syncthreads();

    int jl = tid & 63;
    int j  = blockIdx.x * 64 + jl;
    int wq = tid >> 6;                       // 0..3
    float jx1 = sx1[j], jy1 = sy1[j], jx2 = sx2[j], jy2 = sy2[j], aj = sar[j];
    unsigned* mcol = g_msk + (size_t)b * 32768 + j;

    for (int w = wq; w < 32; w += 4) {
        unsigned bits = 0;
        int imax = j - 32 * w;               // valid bi < imax
        int top = imax > 32 ? 32 : imax;
        for (int bi = 0; bi < top; bi++) {
            int i = 32 * w + bi;             // i < j guaranteed
            float ltx = fmaxf(jx1, sx1[i]), lty = fmaxf(jy1, sy1[i]);
            float rbx = fminf(jx2, sx2[i]), rby = fminf(jy2, sy2[i]);
            float ww = fmaxf(__fsub_rn(rbx, ltx), 0.0f);
            float hh = fmaxf(__fsub_rn(rby, lty), 0.0f);
            float inter = __fmul_rn(ww, hh);
            float den = __fadd_rn(__fsub_rn(__fadd_rn(sar[i], aj), inter), 1e-9f);
            float iou = inter / den;         // IEEE div: bit-match reference compare
            if (iou > IOU_T) bits |= (1u << bi);
        }
        mcol[w * 1024] = bits;               // coalesced over j
    }
}

// ---------- kernel B3: parallel fixpoint NMS + clip/filter + top-300 compaction ----------
__global__ void k_nms(const int* __restrict__ imw, const int* __restrict__ imh,
                      float* __restrict__ out) {
    extern __shared__ unsigned sh[];
    unsigned* cm    = sh;                    // 32768 words (128 KB), [w][j]
    unsigned* kwsA  = sh + 32768;            // 32
    unsigned* kwsB  = sh + 32800;            // 32
    unsigned* wcnt  = sh + 32832;            // 32
    unsigned* wbal  = sh + 32864;            // 32
    int*      ctrl  = (int*)(sh + 32896);    // [0]=total [1]=flag
    float4*   cbox  = (float4*)(sh + 32912); // 300 (16B aligned: 32912*4 % 16 == 0)
    float*    cscore = (float*)(cbox + MAXDET);
    int*      clabel = (int*)(cscore + MAXDET);

    int b = blockIdx.x, tid = threadIdx.x;
    int lane = tid & 31, wid = tid >> 5;

    for (int k = tid; k < 32768; k += 1024) cm[k] = g_msk[(size_t)b * 32768 + k];

    float score = g_tsc[b * KK + tid];
    bool cnd = score > CONF_T;
    unsigned cbal = __ballot_sync(0xffffffffu, cnd);
    if (lane == 0) kwsA[wid] = cbal;
    __syncthreads();

    // fixpoint: keep[j] = cand[j] & !exists(i<j: sup(i,j) & keep[i])
    // converges to the unique greedy solution; cap guarantees termination
    unsigned* cur = kwsA;
    unsigned* nxt = kwsB;
    int wj = wid;                            // cm words needed: w <= j/32 (warp-uniform)
    for (int it = 0; it < 1025; it++) {
        if (tid == 0) ctrl[1] = 0;
        __syncthreads();
        unsigned sup = 0;
        for (int w = 0; w <= wj; w++)
            sup |= cm[w * 1024 + tid] & cur[w];   // lanes->consecutive j: conflict-free; cur[w] broadcast
        bool nk = cnd && (sup == 0u);
        unsigned nb = __ballot_sync(0xffffffffu, nk);
        if (lane == 0) {
            nxt[wid] = nb;
            if (nb != cur[wid]) ctrl[1] = 1;
        }
        __syncthreads();
        if (ctrl[1] == 0) break;
        unsigned* t = cur; cur = nxt; nxt = t;
    }

    bool keep = (cur[wid] >> lane) & 1u;
    float fw = (float)(*imw), fh = (float)(*imh);
    float4 bx = g_tbox[b * KK + tid];
    float x1c = fminf(fmaxf(bx.x, 0.0f), fw);
    float y1c = fminf(fmaxf(bx.y, 0.0f), fh);
    float x2c = fminf(fmaxf(bx.z, 0.0f), fw);
    float y2c = fminf(fmaxf(bx.w, 0.0f), fh);
    float bw  = __fsub_rn(x2c, x1c);
    float bh2 = __fsub_rn(y2c, y1c);
    bool valid = keep && (bw > 0.0f) && (bh2 > 0.0f) && (bw >= 1.0f) && (bh2 >= 1.0f);

    unsigned vb = __ballot_sync(0xffffffffu, valid);
    if (lane == 0) { wcnt[wid] = __popc(vb); wbal[wid] = vb; }
    __syncthreads();
    if (tid == 0) {
        int acc = 0;
        for (int q = 0; q < 32; q++) { int c = wcnt[q]; wcnt[q] = acc; acc += c; }
        ctrl[0] = acc;
    }
    __syncthreads();
    if (valid) {
        int rank = wcnt[wid] + __popc(wbal[wid] & ((1u << lane) - 1u));
        if (rank < MAXDET) {
            cbox[rank]   = make_float4(x1c, y1c, x2c, y2c);
            cscore[rank] = score;
            clabel[rank] = g_tlb[b * KK + tid];
        }
    }
    __syncthreads();

    int total = ctrl[0]; if (total > MAXDET) total = MAXDET;
    if (tid < MAXDET) {
        float4 ob; float os, ol, ov;
        if (tid < total) { ob = cbox[tid]; os = cscore[tid]; ol = (float)clabel[tid]; ov = 1.0f; }
        else             { ob = make_float4(0,0,0,0); os = 0.0f; ol = 0.0f; ov = 0.0f; }
        float* obox = out + ((size_t)b * MAXDET + tid) * 4;
        obox[0] = ob.x; obox[1] = ob.y; obox[2] = ob.z; obox[3] = ob.w;
        out[BB * MAXDET * 4 + b * MAXDET + tid] = os;   // det_scores
        out[BB * MAXDET * 5 + b * MAXDET + tid] = ol;   // det_labels (as f32)
        out[BB * MAXDET * 6 + b * MAXDET + tid] = ov;   // vm (as f32)
    }
}

extern "C" void kernel_launch(void* const* d_in, const int* in_sizes, int n_in,
                              void* d_out, int out_size) {
    const float* pred = (const float*)d_in[0];
    const int*   imh  = (const int*)d_in[1];
    const int*   imw  = (const int*)d_in[2];
    float* out = (float*)d_out;

    cudaFuncSetAttribute((const void*)k_topk,
                         cudaFuncAttributeMaxDynamicSharedMemorySize, 135232);
    cudaFuncSetAttribute((const void*)k_nms,
                         cudaFuncAttributeMaxDynamicSharedMemorySize, 141312);

    k_score<<<(BB * NN) / 256, 256>>>(pred);
    k_topk<<<BB, 1024, 135232>>>(pred);
    k_iou<<<dim3(16, BB), 256>>>();
    k_nms<<<BB, 1024, 141312>>>(imw, imh, out);
}